// round 7
// baseline (speedup 1.0000x reference)
#include <cuda_runtime.h>
#include <cstdint>

#define BB 8
#define NN 256
#define HH 128
#define EPSF 1e-20f

#define GRIDSZ 512
#define TPB    256
#define DEPTH  4          // cp.async stages (power of 2)
#define CHUNK  2          // j-rows per group
#define JHALF  128        // j's per warp (half tile)
#define NCH    (JHALF / CHUNK)

// Scratch (allocation-free rule: __device__ globals)
__device__ float g_Ux[BB * NN * HH];
__device__ float g_Vx[BB * NN * HH];
__device__ unsigned int g_bar;   // monotonic across graph replays

__device__ __forceinline__ float dot4(float4 a, float4 b, float c) {
    return fmaf(a.x, b.x, fmaf(a.y, b.y, fmaf(a.z, b.z, fmaf(a.w, b.w, c))));
}
__device__ __forceinline__ void cp16(uint32_t dst, const float* src) {
    asm volatile("cp.async.cg.shared.global [%0], [%1], 16;" :: "r"(dst), "l"(src));
}
__device__ __forceinline__ void cp_commit() {
    asm volatile("cp.async.commit_group;" ::: "memory");
}
__device__ __forceinline__ void cp_wait2() {
    asm volatile("cp.async.wait_group 2;" ::: "memory");
}

// ---------------------------------------------------------------------------
// ONE fused kernel. grid 512 x 256 thr, launch_bounds(256,4): <=64 regs and
// 41KB smem -> >=4 blocks/SM -> capacity 592 >= 512 -> ALL blocks resident ->
// grid barrier is deadlock-free. Kills the ~14us persistent two-kernel gap.
//
// Phase 1: linear. Block owns 4 rows; thread t: o=t&127, sel=t>>7 (U/V).
// Phase 2: edge. 8 warps = 4 tiles x 2 j-halves. eg streamed via per-THREAD
// 4-stage cp.async ring (each lane cps its own 16B slice -> no syncwarp).
// In-flight bytes no longer reg-limited (~96KB/SM vs ~57KB ceiling R3-R6).
// ---------------------------------------------------------------------------
__global__ __launch_bounds__(TPB, 4) void fused_kernel(
    const float* __restrict__ x, const float* __restrict__ eg,
    const float* __restrict__ mask,
    const float* __restrict__ Uw, const float* __restrict__ Ub,
    const float* __restrict__ Vw, const float* __restrict__ Vb,
    float* __restrict__ out)
{
    __shared__ __align__(16) char pool[8 * DEPTH * CHUNK * 512];  // 32KB; phase1 aliases
    __shared__ float  msk[NN];                                    // 1KB
    __shared__ float4 shr[2][8][32];                              // 8KB

    const int t = threadIdx.x;

    // ---------------- Phase 1: linear ----------------
    {
        float4* xs = reinterpret_cast<float4*>(pool);   // [4][32] float4 = 2KB
        const int r0 = blockIdx.x * 4;
        if (t < 128)
            xs[t] = reinterpret_cast<const float4*>(x)[(size_t)r0 * 32 + t];
        __syncthreads();

        const int o = t & 127, sel = t >> 7;
        const float4* W4 = reinterpret_cast<const float4*>(sel ? Vw : Uw) + (size_t)o * 32;
        const float bias = sel ? Vb[o] : Ub[o];
        float* dst = sel ? g_Vx : g_Ux;

        float a0 = 0.f, a1 = 0.f, a2 = 0.f, a3 = 0.f;
#pragma unroll 8
        for (int k = 0; k < 32; k++) {
            const float4 wv = W4[k];
            a0 = dot4(xs[k], wv, a0);
            a1 = dot4(xs[32 + k], wv, a1);
            a2 = dot4(xs[64 + k], wv, a2);
            a3 = dot4(xs[96 + k], wv, a3);
        }
        dst[(size_t)(r0 + 0) * HH + o] = mask[r0 + 0] * (a0 + bias);
        dst[(size_t)(r0 + 1) * HH + o] = mask[r0 + 1] * (a1 + bias);
        dst[(size_t)(r0 + 2) * HH + o] = mask[r0 + 2] * (a2 + bias);
        dst[(size_t)(r0 + 3) * HH + o] = mask[r0 + 3] * (a3 + bias);
    }

    // ---------------- Grid-wide barrier (monotonic, replay-safe) ----------
    __threadfence();
    __syncthreads();
    if (t == 0) {
        const unsigned int ticket = atomicAdd(&g_bar, 1u);
        const unsigned int target = ticket - (ticket % GRIDSZ) + GRIDSZ;
        for (;;) {
            unsigned int cur;
            asm volatile("ld.acquire.gpu.global.u32 %0, [%1];" : "=r"(cur) : "l"(&g_bar));
            if ((int)(cur - target) >= 0) break;
            __nanosleep(64);
        }
    }
    __syncthreads();

    // ---------------- Phase 2: edge ----------------
    const int lane = t & 31;
    const int w    = t >> 5;          // 0..7
    const int tile = w >> 1;          // 0..3
    const int half = w & 1;           // 0..1
    const int bi   = blockIdx.x * 4 + tile;
    const int b    = bi >> 8;         // 4 | 256 -> same b across block

    msk[t] = mask[b * NN + t];
    __syncthreads();

    char* sbase = pool + w * (DEPTH * CHUNK * 512);   // 4KB per warp
    const uint32_t sb32 = (uint32_t)__cvta_generic_to_shared(sbase) + lane * 16;
    const int j0 = half * JHALF;
    const float*  gp = eg + ((size_t)bi * NN + j0) * HH + lane * 4;
    const float4* vp = reinterpret_cast<const float4*>(g_Vx)
                       + ((size_t)b * NN + j0) * (HH / 4) + lane;
    const float*  mp = msk + j0;

    // prologue: chunks 0..2 in flight
#pragma unroll
    for (int g = 0; g < DEPTH - 1; g++) {
        cp16(sb32 + (g * CHUNK + 0) * 512, gp + (size_t)(g * CHUNK + 0) * HH);
        cp16(sb32 + (g * CHUNK + 1) * 512, gp + (size_t)(g * CHUNK + 1) * HH);
        cp_commit();
    }

    float4 s0 = make_float4(0.f, 0.f, 0.f, 0.f);
    float4 s1 = make_float4(0.f, 0.f, 0.f, 0.f);

#pragma unroll 4
    for (int c = 0; c < NCH; c++) {
        cp_wait2();                                  // chunk c resident
        const int stage = c & (DEPTH - 1);
        const float4* ep = reinterpret_cast<const float4*>(sbase + stage * CHUNK * 512) + lane;
#pragma unroll
        for (int r = 0; r < CHUNK; r++) {
            float4 e = ep[r * 32];                   // own lane's 16B -> no syncwarp
            const float mj = mp[c * CHUNK + r];
            const float4 v = vp[(size_t)(c * CHUNK + r) * 32];
            e.x *= mj; e.y *= mj; e.z *= mj; e.w *= mj;
            s0.x += e.x; s0.y += e.y; s0.z += e.z; s0.w += e.w;
            s1.x = fmaf(e.x, v.x, s1.x);
            s1.y = fmaf(e.y, v.y, s1.y);
            s1.z = fmaf(e.z, v.z, s1.z);
            s1.w = fmaf(e.w, v.w, s1.w);
        }
        const int nc = c + DEPTH - 1;                // next chunk to fetch
        if (nc < NCH) {
            const int ns = nc & (DEPTH - 1);
            cp16(sb32 + (ns * CHUNK + 0) * 512, gp + (size_t)(nc * CHUNK + 0) * HH);
            cp16(sb32 + (ns * CHUNK + 1) * 512, gp + (size_t)(nc * CHUNK + 1) * HH);
        }
        cp_commit();   // empty group in tail keeps wait_group accounting uniform
    }

    shr[0][w][lane] = s0;
    shr[1][w][lane] = s1;
    __syncthreads();

    if (t < 128) {
        const int tl = t >> 5, l = t & 31;
        float4 a0 = shr[0][tl * 2][l];
        float4 a1 = shr[1][tl * 2][l];
        const float4 b0 = shr[0][tl * 2 + 1][l];
        const float4 b1 = shr[1][tl * 2 + 1][l];
        a0.x += b0.x; a0.y += b0.y; a0.z += b0.z; a0.w += b0.w;
        a1.x += b1.x; a1.y += b1.y; a1.z += b1.z; a1.w += b1.w;

        const int bi2 = blockIdx.x * 4 + tl;
        const float mi = msk[bi2 & 255];
        const float4 ux = reinterpret_cast<const float4*>(g_Ux)[(size_t)bi2 * 32 + l];
        float4 o;
        o.x = ux.x + (mi * a1.x) / (EPSF + mi * a0.x);
        o.y = ux.y + (mi * a1.y) / (EPSF + mi * a0.y);
        o.z = ux.z + (mi * a1.z) / (EPSF + mi * a0.z);
        o.w = ux.w + (mi * a1.w) / (EPSF + mi * a0.w);
        reinterpret_cast<float4*>(out)[(size_t)bi2 * 32 + l] = o;
    }
}

extern "C" void kernel_launch(void* const* d_in, const int* in_sizes, int n_in,
                              void* d_out, int out_size)
{
    const float* x   = (const float*)d_in[0];
    const float* eg  = (const float*)d_in[1];
    const float* msk = (const float*)d_in[2];
    const float* Uw  = (const float*)d_in[3];
    const float* Ub  = (const float*)d_in[4];
    const float* Vw  = (const float*)d_in[5];
    const float* Vb  = (const float*)d_in[6];
    float* out = (float*)d_out;

    fused_kernel<<<GRIDSZ, TPB>>>(x, eg, msk, Uw, Ub, Vw, Vb, out);
}